// round 1
// baseline (speedup 1.0000x reference)
#include <cuda_runtime.h>
#include <math.h>

#define B   32
#define T   64
#define S   400
#define DW  512
#define DM  512
#define DE  512
#define DK  64
#define G3  (3*DM)          // 1536
#define PAD_ID 50256

// ---------------- scratch (device globals: no allocation allowed) -------------
__device__ float g_emb[T*B*DW];     // [T,B,DW] gathered embeddings
__device__ float g_pre[B*S*DK];     // enc @ Wc
__device__ float g_h  [B*DM];       // GRU hidden
__device__ float g_ctx[B*DE];       // attention context
__device__ float g_cov[B*S];        // coverage
__device__ float g_gx [B*G3];       // rnn_in @ Wx + bx
__device__ float g_gh [B*G3];       // h @ Wh + bh

// out layout (float32, concatenated tuple):
//   pred        [B,T,256]  @ 0
//   attn_last   [B,S]      @ 524288
//   ctx_f       [B,DE]     @ 537088
//   copy_pred   [B,T,S]    @ 553472
//   copy_gate   [B,T]      @ 1372672
//   coverage    [B,T]      @ 1374720
#define OFF_PRED      0
#define OFF_ATTNLAST  524288
#define OFF_CTXF      537088
#define OFF_COPY      553472
#define OFF_GATE      1372672
#define OFF_COVP      1374720

// ---------------- one-time kernels -------------------------------------------

__global__ void k_embed(const int* __restrict__ tgt, const float* __restrict__ word_emb)
{
    int row = blockIdx.x;                 // row = t*B + b
    int t = row / B, b = row % B;
    int id = tgt[b*T + t];
    const float4* src = (const float4*)(word_emb + (long long)id * DW);
    float4* dst = (float4*)(g_emb + (long long)row * DW);
    dst[threadIdx.x] = src[threadIdx.x];  // 128 threads * float4 = 512 floats
}

__global__ void k_pre(const float* __restrict__ enc, const float* __restrict__ Wc)
{
    // pre[row, n] = sum_k enc[row,k] * Wc[k,n];  row = b*S+s
    int row = blockIdx.x * 16 + threadIdx.y;        // blockDim (16,16), grid 800
    int n   = threadIdx.x * 4;
    const float* a = enc + (long long)row * DE;
    float4 acc = make_float4(0.f,0.f,0.f,0.f);
#pragma unroll 4
    for (int k = 0; k < DE; k++) {
        float av = a[k];
        float4 wv = *(const float4*)(Wc + k*DK + n);
        acc.x = fmaf(av, wv.x, acc.x); acc.y = fmaf(av, wv.y, acc.y);
        acc.z = fmaf(av, wv.z, acc.z); acc.w = fmaf(av, wv.w, acc.w);
    }
    *(float4*)(g_pre + (long long)row*DK + n) = acc;
}

__global__ void k_init(const float* __restrict__ hidden,
                       const float* __restrict__ W_init,
                       const float* __restrict__ b_init)
{
    int idx = blockIdx.x * 256 + threadIdx.x;   // 0..16383
    int b = idx / DM, j = idx % DM;
    const float* a = hidden + b * DE;
    float acc = b_init[j];
#pragma unroll 4
    for (int k = 0; k < DE; k++)
        acc = fmaf(a[k], W_init[k*DM + j], acc);
    g_h[idx]   = tanhf(acc);
    g_ctx[idx] = 0.f;
    if (idx < B*S) g_cov[idx] = 0.f;
}

// ---------------- per-step kernels -------------------------------------------

// gx[b, 0..1535] = concat(e, ctx) @ Wx + bx ;  gh[b, 0..1535] = h @ Wh + bh
// grid (24, 4), block (32, 8). blockIdx.x < 12 -> gx tile; else gh tile.
__global__ void k_gxgh(int t,
                       const float* __restrict__ Wx, const float* __restrict__ Wh,
                       const float* __restrict__ bx, const float* __restrict__ bh)
{
    int b    = blockIdx.y * 8 + threadIdx.y;
    int ncol = blockIdx.x * 128 + threadIdx.x * 4;
    float4 acc = make_float4(0.f,0.f,0.f,0.f);

    if (ncol < G3) {
        const float* __restrict__ e = g_emb + ((long long)t*B + b) * DW;
        const float* __restrict__ c = g_ctx + b * DE;
        const float* __restrict__ w = Wx + ncol;
#pragma unroll 4
        for (int k = 0; k < DW; k++) {
            float a = e[k];
            float4 wv = *(const float4*)(w + (size_t)k * G3);
            acc.x = fmaf(a,wv.x,acc.x); acc.y = fmaf(a,wv.y,acc.y);
            acc.z = fmaf(a,wv.z,acc.z); acc.w = fmaf(a,wv.w,acc.w);
        }
        const float* __restrict__ w2 = Wx + (size_t)DW * G3 + ncol;
#pragma unroll 4
        for (int k = 0; k < DE; k++) {
            float a = c[k];
            float4 wv = *(const float4*)(w2 + (size_t)k * G3);
            acc.x = fmaf(a,wv.x,acc.x); acc.y = fmaf(a,wv.y,acc.y);
            acc.z = fmaf(a,wv.z,acc.z); acc.w = fmaf(a,wv.w,acc.w);
        }
        float4 bb = *(const float4*)(bx + ncol);
        acc.x += bb.x; acc.y += bb.y; acc.z += bb.z; acc.w += bb.w;
        *(float4*)(g_gx + (long long)b*G3 + ncol) = acc;
    } else {
        int n = ncol - G3;
        const float* __restrict__ h = g_h + b * DM;
        const float* __restrict__ w = Wh + n;
#pragma unroll 4
        for (int k = 0; k < DM; k++) {
            float a = h[k];
            float4 wv = *(const float4*)(w + (size_t)k * G3);
            acc.x = fmaf(a,wv.x,acc.x); acc.y = fmaf(a,wv.y,acc.y);
            acc.z = fmaf(a,wv.z,acc.z); acc.w = fmaf(a,wv.w,acc.w);
        }
        float4 bb = *(const float4*)(bh + n);
        acc.x += bb.x; acc.y += bb.y; acc.z += bb.z; acc.w += bb.w;
        *(float4*)(g_gh + (long long)b*G3 + n) = acc;
    }
}

// per-b megakernel: gates -> h_new, q, scores, softmax, coverage, ctx, copy_gate
// grid B, block 256
__global__ void k_attn(int t,
                       const int*   __restrict__ src_seq,
                       const float* __restrict__ enc,
                       const float* __restrict__ Wq,
                       const float* __restrict__ w_cov,
                       const float* __restrict__ v_att,
                       const float* __restrict__ W_copy,
                       const float* __restrict__ b_copy,
                       float* __restrict__ out)
{
    int b   = blockIdx.x;
    int tid = threadIdx.x;

    __shared__ float sh[DM];          // h_new
    __shared__ float sq[DK];
    __shared__ float sqp[4][DK];
    __shared__ float swc[DK];
    __shared__ float sva[DK];
    __shared__ float ss[S];           // scores -> attn
    __shared__ float red[256];
    __shared__ float sctx[DE];        // new context
    __shared__ float spart[DE];       // second-half partials

    // ---- phase 1: GRU gates -> h_new (also persist to g_h for next step) ----
    for (int j = tid; j < DM; j += 256) {
        float gxr = g_gx[b*G3 + j],        ghr = g_gh[b*G3 + j];
        float gxz = g_gx[b*G3 + DM + j],   ghz = g_gh[b*G3 + DM + j];
        float gxn = g_gx[b*G3 + 2*DM + j], ghn = g_gh[b*G3 + 2*DM + j];
        float r = 1.f / (1.f + expf(-(gxr + ghr)));
        float z = 1.f / (1.f + expf(-(gxz + ghz)));
        float n = tanhf(gxn + r * ghn);
        float ho = g_h[b*DM + j];
        float hn = (1.f - z) * n + z * ho;
        sh[j] = hn;
        g_h[b*DM + j] = hn;
    }
    __syncthreads();

    // ---- phase 2: q = h_new @ Wq  (split-k over 4 parts) ----
    {
        int j = tid & 63, p = tid >> 6;
        float acc = 0.f;
        for (int k = p*128; k < (p+1)*128; k++)
            acc = fmaf(sh[k], Wq[k*DK + j], acc);
        sqp[p][j] = acc;
        if (tid < DK)              swc[tid]      = w_cov[tid];
        else if (tid < 2*DK)       sva[tid - DK] = v_att[tid - DK];
    }
    __syncthreads();
    if (tid < DK) sq[tid] = sqp[0][tid] + sqp[1][tid] + sqp[2][tid] + sqp[3][tid];
    __syncthreads();

    // ---- phase 3: attention scores with coverage + pad mask ----
    for (int s = tid; s < S; s += 256) {
        float cv = g_cov[b*S + s];
        const float* pr = g_pre + ((long long)b*S + s) * DK;
        float acc = 0.f;
#pragma unroll 8
        for (int k = 0; k < DK; k++)
            acc = fmaf(tanhf(pr[k] + sq[k] + cv * swc[k]), sva[k], acc);
        if (src_seq[b*S + s] == PAD_ID) acc = -1e9f;
        ss[s] = acc;
    }
    __syncthreads();

    // ---- softmax over S ----
    float m = -1e30f;
    for (int s = tid; s < S; s += 256) m = fmaxf(m, ss[s]);
    red[tid] = m; __syncthreads();
    for (int w = 128; w > 0; w >>= 1) {
        if (tid < w) red[tid] = fmaxf(red[tid], red[tid+w]);
        __syncthreads();
    }
    m = red[0]; __syncthreads();

    float sum = 0.f;
    for (int s = tid; s < S; s += 256) { float e = expf(ss[s] - m); ss[s] = e; sum += e; }
    red[tid] = sum; __syncthreads();
    for (int w = 128; w > 0; w >>= 1) {
        if (tid < w) red[tid] += red[tid+w];
        __syncthreads();
    }
    float inv = 1.f / red[0]; __syncthreads();

    // ---- attn, coverage update, outputs ----
    float cl = 0.f;
    float tden = fmaxf((float)t, 1.f);
    for (int s = tid; s < S; s += 256) {
        float a = ss[s] * inv; ss[s] = a;
        float cv = g_cov[b*S + s];
        cl += fminf(a, cv / tden);
        g_cov[b*S + s] = cv + a;
        out[OFF_COPY + (long long)b*T*S + (long long)t*S + s] = a;
        if (t == T-1) out[OFF_ATTNLAST + b*S + s] = a;
    }
    red[tid] = cl; __syncthreads();
    for (int w = 128; w > 0; w >>= 1) {
        if (tid < w) red[tid] += red[tid+w];
        __syncthreads();
    }
    if (tid == 0) out[OFF_COVP + b*T + t] = red[0];
    __syncthreads();

    // ---- new_ctx = attn @ enc  (256 thr: 128 float4 cols x 2 s-halves) ----
    {
        int d4 = tid & 127;
        int half = tid >> 7;
        const float4* e4 = (const float4*)(enc + (long long)b*S*DE);
        float4 acc = make_float4(0.f,0.f,0.f,0.f);
        int s0 = half * 200, s1 = s0 + 200;
        for (int s = s0; s < s1; s++) {
            float a = ss[s];
            float4 v = e4[(long long)s*(DE/4) + d4];
            acc.x = fmaf(a,v.x,acc.x); acc.y = fmaf(a,v.y,acc.y);
            acc.z = fmaf(a,v.z,acc.z); acc.w = fmaf(a,v.w,acc.w);
        }
        if (half == 1) {
            spart[d4*4+0]=acc.x; spart[d4*4+1]=acc.y;
            spart[d4*4+2]=acc.z; spart[d4*4+3]=acc.w;
        }
        __syncthreads();
        if (half == 0) {
            acc.x += spart[d4*4+0]; acc.y += spart[d4*4+1];
            acc.z += spart[d4*4+2]; acc.w += spart[d4*4+3];
            sctx[d4*4+0]=acc.x; sctx[d4*4+1]=acc.y;
            sctx[d4*4+2]=acc.z; sctx[d4*4+3]=acc.w;
            *(float4*)(g_ctx + b*DE + d4*4) = acc;
            if (t == T-1)
                *(float4*)(out + OFF_CTXF + b*DE + d4*4) = acc;
        }
        __syncthreads();
    }

    // ---- copy_gate = sigmoid([h_new, new_ctx] @ W_copy + b_copy) ----
    {
        float g = 0.f;
        for (int k = tid; k < DM; k += 256) g = fmaf(sh[k],   W_copy[k],      g);
        for (int k = tid; k < DE; k += 256) g = fmaf(sctx[k], W_copy[DM + k], g);
        red[tid] = g; __syncthreads();
        for (int w = 128; w > 0; w >>= 1) {
            if (tid < w) red[tid] += red[tid+w];
            __syncthreads();
        }
        if (tid == 0) {
            float v = red[0] + b_copy[0];
            out[OFF_GATE + b*T + t] = 1.f / (1.f + expf(-v));
        }
    }
}

// readout = [e, h_new, new_ctx] @ W_read + b_read; maxout pool 2 -> pred
// grid (4,4), block (32,8)
__global__ void k_readout(int t,
                          const float* __restrict__ W_read,
                          const float* __restrict__ b_read,
                          float* __restrict__ out)
{
    int b = blockIdx.y * 8 + threadIdx.y;
    int n = (blockIdx.x * 32 + threadIdx.x) * 4;   // 0..508
    const float* __restrict__ e = g_emb + ((long long)t*B + b) * DW;
    const float* __restrict__ h = g_h   + b * DM;
    const float* __restrict__ c = g_ctx + b * DE;
    float4 acc = *(const float4*)(b_read + n);
    const float* __restrict__ w = W_read + n;
#pragma unroll 4
    for (int k = 0; k < DW; k++) {
        float a = e[k];
        float4 wv = *(const float4*)(w + (size_t)k * DM);
        acc.x = fmaf(a,wv.x,acc.x); acc.y = fmaf(a,wv.y,acc.y);
        acc.z = fmaf(a,wv.z,acc.z); acc.w = fmaf(a,wv.w,acc.w);
    }
    const float* __restrict__ w2 = W_read + (size_t)DW*DM + n;
#pragma unroll 4
    for (int k = 0; k < DM; k++) {
        float a = h[k];
        float4 wv = *(const float4*)(w2 + (size_t)k * DM);
        acc.x = fmaf(a,wv.x,acc.x); acc.y = fmaf(a,wv.y,acc.y);
        acc.z = fmaf(a,wv.z,acc.z); acc.w = fmaf(a,wv.w,acc.w);
    }
    const float* __restrict__ w3 = W_read + (size_t)(DW+DM)*DM + n;
#pragma unroll 4
    for (int k = 0; k < DE; k++) {
        float a = c[k];
        float4 wv = *(const float4*)(w3 + (size_t)k * DM);
        acc.x = fmaf(a,wv.x,acc.x); acc.y = fmaf(a,wv.y,acc.y);
        acc.z = fmaf(a,wv.z,acc.z); acc.w = fmaf(a,wv.w,acc.w);
    }
    float m0 = fmaxf(acc.x, acc.y);
    float m1 = fmaxf(acc.z, acc.w);
    long long base = OFF_PRED + ((long long)b*T + t) * (DM/2);
    out[base + n/2]     = m0;
    out[base + n/2 + 1] = m1;
}

// ---------------- launch ------------------------------------------------------

extern "C" void kernel_launch(void* const* d_in, const int* in_sizes, int n_in,
                              void* d_out, int out_size)
{
    const int*   tgt      = (const int*)  d_in[0];
    const int*   src      = (const int*)  d_in[1];
    const float* enc      = (const float*)d_in[2];
    const float* hidden   = (const float*)d_in[3];
    const float* word_emb = (const float*)d_in[4];
    const float* W_init   = (const float*)d_in[5];
    const float* b_init   = (const float*)d_in[6];
    const float* Wx       = (const float*)d_in[7];
    const float* Wh       = (const float*)d_in[8];
    const float* bx       = (const float*)d_in[9];
    const float* bh       = (const float*)d_in[10];
    const float* Wc       = (const float*)d_in[11];
    const float* Wq       = (const float*)d_in[12];
    const float* w_cov    = (const float*)d_in[13];
    const float* v_att    = (const float*)d_in[14];
    const float* W_copy   = (const float*)d_in[15];
    const float* b_copy   = (const float*)d_in[16];
    const float* W_read   = (const float*)d_in[17];
    const float* b_read   = (const float*)d_in[18];
    float* out = (float*)d_out;

    k_embed<<<T*B, 128>>>(tgt, word_emb);
    k_pre<<<(B*S)/16, dim3(16,16)>>>(enc, Wc);
    k_init<<<(B*DM)/256, 256>>>(hidden, W_init, b_init);

    for (int t = 0; t < T; t++) {
        k_gxgh<<<dim3(24,4), dim3(32,8)>>>(t, Wx, Wh, bx, bh);
        k_attn<<<B, 256>>>(t, src, enc, Wq, w_cov, v_att, W_copy, b_copy, out);
        k_readout<<<dim3(4,4), dim3(32,8)>>>(t, W_read, b_read, out);
    }
}

// round 2
// speedup vs baseline: 1.0681x; 1.0681x over previous
#include <cuda_runtime.h>
#include <math.h>

#define B   32
#define T   64
#define S   400
#define DW  512
#define DM  512
#define DE  512
#define DK  64
#define G3  (3*DM)          // 1536
#define PAD_ID 50256

// ---------------- scratch (device globals) ------------------------------------
__device__ float g_emb[T*B*DW];     // [T,B,DW]
__device__ float g_pre[B*S*DK];     // enc @ Wc
__device__ float g_h  [B*DM];
__device__ float g_ctx[B*DE];
__device__ float g_cov[B*S];
__device__ float g_gx [B*G3];
__device__ float g_gh [B*G3];

// out layout (float32):
#define OFF_PRED      0
#define OFF_ATTNLAST  524288
#define OFF_CTXF      537088
#define OFF_COPY      553472
#define OFF_GATE      1372672
#define OFF_COVP      1374720

// ---------------- one-time kernels -------------------------------------------

__global__ void k_embed(const int* __restrict__ tgt, const float* __restrict__ word_emb)
{
    int row = blockIdx.x;                 // row = t*B + b
    int t = row / B, b = row % B;
    int id = tgt[b*T + t];
    const float4* src = (const float4*)(word_emb + (long long)id * DW);
    float4* dst = (float4*)(g_emb + (long long)row * DW);
    dst[threadIdx.x] = src[threadIdx.x];  // 128 threads * float4
}

__global__ void k_pre(const float* __restrict__ enc, const float* __restrict__ Wc)
{
    int row = blockIdx.x * 16 + threadIdx.y;        // grid 800, block (16,16)
    int n   = threadIdx.x * 4;
    const float* a = enc + (long long)row * DE;
    float4 acc = make_float4(0.f,0.f,0.f,0.f);
#pragma unroll 8
    for (int k = 0; k < DE; k++) {
        float av = a[k];
        float4 wv = *(const float4*)(Wc + k*DK + n);
        acc.x = fmaf(av, wv.x, acc.x); acc.y = fmaf(av, wv.y, acc.y);
        acc.z = fmaf(av, wv.z, acc.z); acc.w = fmaf(av, wv.w, acc.w);
    }
    *(float4*)(g_pre + (long long)row*DK + n) = acc;
}

__global__ void k_init(const float* __restrict__ hidden,
                       const float* __restrict__ W_init,
                       const float* __restrict__ b_init)
{
    int idx = blockIdx.x * 256 + threadIdx.x;   // 0..16383
    int b = idx / DM, j = idx % DM;
    const float* a = hidden + b * DE;
    float acc = b_init[j];
#pragma unroll 8
    for (int k = 0; k < DE; k++)
        acc = fmaf(a[k], W_init[k*DM + j], acc);
    g_h[idx]   = tanhf(acc);
    g_ctx[idx] = 0.f;
    if (idx < B*S) g_cov[idx] = 0.f;
}

// ---------------- fused per-step GEMM kernel ----------------------------------
// Block (32,8) = 256 thr. Each thread: 4 cols (float4) x 4 batch rows (16 acc).
// blockIdx.x: [0,12)  gx  = concat(e_t, ctx) @ Wx + bx   (K=1024, cols 1536)
//             [12,24) gh  = h @ Wh + bh                  (K=512,  cols 1536)
//             [24,28) readout for step t-1 + maxout      (K=1536, cols 512)
__global__ void k_big(int t,
                      const float* __restrict__ Wx, const float* __restrict__ Wh,
                      const float* __restrict__ bx, const float* __restrict__ bh,
                      const float* __restrict__ W_read, const float* __restrict__ b_read,
                      float* __restrict__ out)
{
    int bid = blockIdx.x;
    int tx  = threadIdx.x;           // 0..31  (float4 column within 128-col tile)
    int ty  = threadIdx.y;           // 0..7   (batch group of 4)
    int tid = ty*32 + tx;

    __shared__ float sA[32][128];    // activation chunk [b][k] 16KB

    const float* W; const float* bias;
    int ncol0, K, stride, mode;
    if (bid < 12) {
        if (t >= T) return;
        mode = 0; W = Wx; bias = bx; ncol0 = bid*128; K = 1024; stride = G3;
    } else if (bid < 24) {
        if (t >= T) return;
        mode = 1; W = Wh; bias = bh; ncol0 = (bid-12)*128; K = 512; stride = G3;
    } else {
        if (t == 0) return;
        mode = 2; W = W_read; bias = b_read; ncol0 = (bid-24)*128; K = 1536; stride = DM;
    }

    float4 acc[4];
#pragma unroll
    for (int i = 0; i < 4; i++) acc[i] = make_float4(0.f,0.f,0.f,0.f);

    int n = ncol0 + tx*4;

    for (int k0 = 0; k0 < K; k0 += 128) {
        // cooperative load of A chunk [32][128]
#pragma unroll
        for (int j = 0; j < 4; j++) {
            int f  = tid + j*256;        // float4 index 0..1023
            int bb = f >> 5;             // batch row
            int kk = (f & 31) * 4;       // float offset within chunk
            const float* src;
            if (mode == 0) {
                src = (k0 < 512) ? (g_emb + ((long long)t*B + bb)*DW + k0)
                                 : (g_ctx + bb*DE + (k0 - 512));
            } else if (mode == 1) {
                src = g_h + bb*DM + k0;
            } else {
                if (k0 < 512)       src = g_emb + ((long long)(t-1)*B + bb)*DW + k0;
                else if (k0 < 1024) src = g_h   + bb*DM + (k0 - 512);
                else                src = g_ctx + bb*DE + (k0 - 1024);
            }
            *(float4*)(&sA[bb][kk]) = *(const float4*)(src + kk);
        }
        __syncthreads();

        const float* wp = W + (size_t)k0 * stride + n;
#pragma unroll 4
        for (int kk = 0; kk < 128; kk++) {
            float4 wv = *(const float4*)(wp + (size_t)kk * stride);
#pragma unroll
            for (int i = 0; i < 4; i++) {
                float a = sA[ty*4 + i][kk];
                acc[i].x = fmaf(a, wv.x, acc[i].x);
                acc[i].y = fmaf(a, wv.y, acc[i].y);
                acc[i].z = fmaf(a, wv.z, acc[i].z);
                acc[i].w = fmaf(a, wv.w, acc[i].w);
            }
        }
        __syncthreads();
    }

    float4 bb4 = *(const float4*)(bias + n);
    if (mode == 0) {
#pragma unroll
        for (int i = 0; i < 4; i++) {
            int b = ty*4 + i;
            float4 v = make_float4(acc[i].x + bb4.x, acc[i].y + bb4.y,
                                   acc[i].z + bb4.z, acc[i].w + bb4.w);
            *(float4*)(g_gx + (long long)b*G3 + n) = v;
        }
    } else if (mode == 1) {
#pragma unroll
        for (int i = 0; i < 4; i++) {
            int b = ty*4 + i;
            float4 v = make_float4(acc[i].x + bb4.x, acc[i].y + bb4.y,
                                   acc[i].z + bb4.z, acc[i].w + bb4.w);
            *(float4*)(g_gh + (long long)b*G3 + n) = v;
        }
    } else {
#pragma unroll
        for (int i = 0; i < 4; i++) {
            int b = ty*4 + i;
            float m0 = fmaxf(acc[i].x + bb4.x, acc[i].y + bb4.y);
            float m1 = fmaxf(acc[i].z + bb4.z, acc[i].w + bb4.w);
            long long base = OFF_PRED + ((long long)b*T + (t-1)) * (DM/2);
            float2 v = make_float2(m0, m1);
            *(float2*)(out + base + n/2) = v;
        }
    }
}

// ---------------- per-step attention megakernel (512 thr / batch row) ---------
__global__ void k_attn(int t,
                       const int*   __restrict__ src_seq,
                       const float* __restrict__ enc,
                       const float* __restrict__ Wq,
                       const float* __restrict__ w_cov,
                       const float* __restrict__ v_att,
                       const float* __restrict__ W_copy,
                       const float* __restrict__ b_copy,
                       float* __restrict__ out)
{
    int b   = blockIdx.x;
    int tid = threadIdx.x;                 // 0..511

    __shared__ float sh[DM];
    __shared__ float sq[DK];
    __shared__ float sqp[8][DK];
    __shared__ float swc[DK];
    __shared__ float sva[DK];
    __shared__ float ss[S];
    __shared__ float red[512];
    __shared__ float sctx[DE];
    __shared__ float spart[3][DE];

    // ---- GRU gates -> h_new ----
    {
        int j = tid;   // 512 threads, DM=512
        float gxr = g_gx[b*G3 + j],        ghr = g_gh[b*G3 + j];
        float gxz = g_gx[b*G3 + DM + j],   ghz = g_gh[b*G3 + DM + j];
        float gxn = g_gx[b*G3 + 2*DM + j], ghn = g_gh[b*G3 + 2*DM + j];
        float r = 1.f / (1.f + expf(-(gxr + ghr)));
        float z = 1.f / (1.f + expf(-(gxz + ghz)));
        float nn = tanhf(gxn + r * ghn);
        float ho = g_h[b*DM + j];
        float hn = (1.f - z) * nn + z * ho;
        sh[j] = hn;
        g_h[b*DM + j] = hn;
    }
    __syncthreads();

    // ---- q = h_new @ Wq  (split-K over 8 parts) ----
    {
        int j = tid & 63, p = tid >> 6;     // p 0..7
        float acc = 0.f;
        for (int k = p*64; k < (p+1)*64; k++)
            acc = fmaf(sh[k], Wq[k*DK + j], acc);
        sqp[p][j] = acc;
        if (tid < DK)          swc[tid]      = w_cov[tid];
        else if (tid < 2*DK)   sva[tid - DK] = v_att[tid - DK];
    }
    __syncthreads();
    if (tid < DK) {
        float s = 0.f;
#pragma unroll
        for (int p = 0; p < 8; p++) s += sqp[p][tid];
        sq[tid] = s;
    }
    __syncthreads();

    // ---- attention scores with coverage + pad mask ----
    if (tid < S) {
        int s = tid;
        float cv = g_cov[b*S + s];
        const float* pr = g_pre + ((long long)b*S + s) * DK;
        float acc = 0.f;
#pragma unroll 8
        for (int k = 0; k < DK; k++)
            acc = fmaf(tanhf(pr[k] + sq[k] + cv * swc[k]), sva[k], acc);
        if (src_seq[b*S + s] == PAD_ID) acc = -1e9f;
        ss[s] = acc;
    }
    __syncthreads();

    // ---- softmax over S ----
    float m = (tid < S) ? ss[tid] : -1e30f;
    red[tid] = m; __syncthreads();
    for (int w = 256; w > 0; w >>= 1) {
        if (tid < w) red[tid] = fmaxf(red[tid], red[tid+w]);
        __syncthreads();
    }
    m = red[0]; __syncthreads();

    float sum = 0.f;
    if (tid < S) { float e = expf(ss[tid] - m); ss[tid] = e; sum = e; }
    red[tid] = sum; __syncthreads();
    for (int w = 256; w > 0; w >>= 1) {
        if (tid < w) red[tid] += red[tid+w];
        __syncthreads();
    }
    float inv = 1.f / red[0]; __syncthreads();

    // ---- attn, coverage update, outputs ----
    float cl = 0.f;
    float tden = fmaxf((float)t, 1.f);
    if (tid < S) {
        int s = tid;
        float a = ss[s] * inv; ss[s] = a;
        float cv = g_cov[b*S + s];
        cl = fminf(a, cv / tden);
        g_cov[b*S + s] = cv + a;
        out[OFF_COPY + (long long)b*T*S + (long long)t*S + s] = a;
        if (t == T-1) out[OFF_ATTNLAST + b*S + s] = a;
    }
    red[tid] = cl; __syncthreads();
    for (int w = 256; w > 0; w >>= 1) {
        if (tid < w) red[tid] += red[tid+w];
        __syncthreads();
    }
    if (tid == 0) out[OFF_COVP + b*T + t] = red[0];
    __syncthreads();

    // ---- new_ctx = attn @ enc  (128 float4 cols x 4 s-quarters) ----
    {
        int d4 = tid & 127;
        int q  = tid >> 7;                      // 0..3
        const float4* e4 = (const float4*)(enc + (long long)b*S*DE);
        float4 acc = make_float4(0.f,0.f,0.f,0.f);
        int s0 = q * 100, s1 = s0 + 100;
#pragma unroll 4
        for (int s = s0; s < s1; s++) {
            float a = ss[s];
            float4 v = e4[(long long)s*(DE/4) + d4];
            acc.x = fmaf(a,v.x,acc.x); acc.y = fmaf(a,v.y,acc.y);
            acc.z = fmaf(a,v.z,acc.z); acc.w = fmaf(a,v.w,acc.w);
        }
        if (q > 0) *(float4*)(&spart[q-1][d4*4]) = acc;
        __syncthreads();
        if (q == 0) {
#pragma unroll
            for (int p = 0; p < 3; p++) {
                float4 v = *(float4*)(&spart[p][d4*4]);
                acc.x += v.x; acc.y += v.y; acc.z += v.z; acc.w += v.w;
            }
            *(float4*)(&sctx[d4*4]) = acc;
            *(float4*)(g_ctx + b*DE + d4*4) = acc;
            if (t == T-1)
                *(float4*)(out + OFF_CTXF + b*DE + d4*4) = acc;
        }
        __syncthreads();
    }

    // ---- copy_gate = sigmoid([h_new, new_ctx] @ W_copy + b_copy) ----
    {
        float g = 0.f;
        for (int k = tid; k < DM; k += 512) g = fmaf(sh[k],   W_copy[k],      g);
        for (int k = tid; k < DE; k += 512) g = fmaf(sctx[k], W_copy[DM + k], g);
        red[tid] = g; __syncthreads();
        for (int w = 256; w > 0; w >>= 1) {
            if (tid < w) red[tid] += red[tid+w];
            __syncthreads();
        }
        if (tid == 0) {
            float v = red[0] + b_copy[0];
            out[OFF_GATE + b*T + t] = 1.f / (1.f + expf(-v));
        }
    }
}

// ---------------- launch ------------------------------------------------------

extern "C" void kernel_launch(void* const* d_in, const int* in_sizes, int n_in,
                              void* d_out, int out_size)
{
    const int*   tgt      = (const int*)  d_in[0];
    const int*   src      = (const int*)  d_in[1];
    const float* enc      = (const float*)d_in[2];
    const float* hidden   = (const float*)d_in[3];
    const float* word_emb = (const float*)d_in[4];
    const float* W_init   = (const float*)d_in[5];
    const float* b_init   = (const float*)d_in[6];
    const float* Wx       = (const float*)d_in[7];
    const float* Wh       = (const float*)d_in[8];
    const float* bx       = (const float*)d_in[9];
    const float* bh       = (const float*)d_in[10];
    const float* Wc       = (const float*)d_in[11];
    const float* Wq       = (const float*)d_in[12];
    const float* w_cov    = (const float*)d_in[13];
    const float* v_att    = (const float*)d_in[14];
    const float* W_copy   = (const float*)d_in[15];
    const float* b_copy   = (const float*)d_in[16];
    const float* W_read   = (const float*)d_in[17];
    const float* b_read   = (const float*)d_in[18];
    float* out = (float*)d_out;

    k_embed<<<T*B, 128>>>(tgt, word_emb);
    k_pre<<<(B*S)/16, dim3(16,16)>>>(enc, Wc);
    k_init<<<(B*DM)/256, 256>>>(hidden, W_init, b_init);

    for (int t = 0; t < T; t++) {
        k_big<<<28, dim3(32,8)>>>(t, Wx, Wh, bx, bh, W_read, b_read, out);
        k_attn<<<B, 512>>>(t, src, enc, Wq, w_cov, v_att, W_copy, b_copy, out);
    }
    // final readout for t = T-1
    k_big<<<28, dim3(32,8)>>>(T, Wx, Wh, bx, bh, W_read, b_read, out);
}

// round 3
// speedup vs baseline: 4.3334x; 4.0570x over previous
#include <cuda_runtime.h>
#include <math.h>

#define B   32
#define T   64
#define S   400
#define DW  512
#define DM  512
#define DE  512
#define DK  64
#define G3  (3*DM)          // 1536
#define PAD_ID 50256

// ---------------- scratch (device globals) ------------------------------------
__device__ float g_emb[T*B*DW];       // [T,B,DW]
__device__ float g_pre[B*S*DK];       // enc @ Wc
__device__ float g_h  [B*DM];
__device__ float g_ctx[B*DE];
__device__ float g_cov[B*S];
__device__ float g_gxp[4][B*G3];      // gx split-K partials
__device__ float g_ghp[2][B*G3];      // gh split-K partials
__device__ float g_rop[6][B*DM];      // readout split-K partials

// out layout (float32):
#define OFF_PRED      0
#define OFF_ATTNLAST  524288
#define OFF_CTXF      537088
#define OFF_COPY      553472
#define OFF_GATE      1372672
#define OFF_COVP      1374720

__device__ __forceinline__ float tanh_fast(float x) {
    float y; asm("tanh.approx.f32 %0, %1;" : "=f"(y) : "f"(x)); return y;
}
__device__ __forceinline__ float sigmoid_fast(float x) {
    return 1.f / (1.f + __expf(-x));
}

// ---------------- one-time kernels -------------------------------------------

__global__ void k_embed(const int* __restrict__ tgt, const float* __restrict__ word_emb)
{
    int row = blockIdx.x;                 // row = t*B + b
    int t = row / B, b = row % B;
    int id = tgt[b*T + t];
    const float4* src = (const float4*)(word_emb + (long long)id * DW);
    float4* dst = (float4*)(g_emb + (long long)row * DW);
    dst[threadIdx.x] = src[threadIdx.x];  // 128 threads * float4
}

__global__ void k_pre(const float* __restrict__ enc, const float* __restrict__ Wc)
{
    int row = blockIdx.x * 16 + threadIdx.y;        // grid 800, block (16,16)
    int n   = threadIdx.x * 4;
    const float* a = enc + (long long)row * DE;
    float4 acc = make_float4(0.f,0.f,0.f,0.f);
#pragma unroll 8
    for (int k = 0; k < DE; k++) {
        float av = a[k];
        float4 wv = *(const float4*)(Wc + k*DK + n);
        acc.x = fmaf(av, wv.x, acc.x); acc.y = fmaf(av, wv.y, acc.y);
        acc.z = fmaf(av, wv.z, acc.z); acc.w = fmaf(av, wv.w, acc.w);
    }
    *(float4*)(g_pre + (long long)row*DK + n) = acc;
}

__global__ void k_init(const float* __restrict__ hidden,
                       const float* __restrict__ W_init,
                       const float* __restrict__ b_init)
{
    int idx = blockIdx.x * 256 + threadIdx.x;   // 0..16383
    int b = idx / DM, j = idx % DM;
    const float* a = hidden + b * DE;
    float acc = b_init[j];
#pragma unroll 8
    for (int k = 0; k < DE; k++)
        acc = fmaf(a[k], W_init[k*DM + j], acc);
    g_h[idx]   = tanhf(acc);
    g_ctx[idx] = 0.f;
    if (idx < B*S) g_cov[idx] = 0.f;
}

// ---------------- per-step GEMM kernel (split-K, 192 blocks) -------------------
// block (16,16). thread: 4 n-cols (tx*4) x 2 batch rows (ty*2). K chunk = 256.
// bid [0,96):    gx   tiles 24 x ksplit 4   (Wx, K=1024)
// bid [96,144):  gh   tiles 24 x ksplit 2   (Wh, K=512)
// bid [144,192): ro   tiles  8 x ksplit 6   (W_read, K=1536) for step t-1
__global__ void k_big(int t,
                      const float* __restrict__ Wx, const float* __restrict__ Wh,
                      const float* __restrict__ W_read)
{
    __shared__ float sAct[32][260];

    int bid = blockIdx.x;
    int tx = threadIdx.x;      // 0..15
    int ty = threadIdx.y;      // 0..15
    int tid = ty*16 + tx;

    const float* W; int n0, k0, stride, ks, mode;
    if (bid < 96) {
        if (t >= T) return;
        mode = 0; ks = bid & 3; n0 = (bid >> 2) * 64; k0 = ks * 256;
        W = Wx; stride = G3;
    } else if (bid < 144) {
        if (t >= T) return;
        int r = bid - 96;
        mode = 1; ks = r & 1; n0 = (r >> 1) * 64; k0 = ks * 256;
        W = Wh; stride = G3;
    } else {
        if (t == 0) return;
        int r = bid - 144;
        mode = 2; ks = r % 6; n0 = (r / 6) * 64; k0 = ks * 256;
        W = W_read; stride = DM;
    }

    // cooperative load of act chunk [32][256]
#pragma unroll
    for (int j = 0; j < 8; j++) {
        int f   = tid + j * 256;
        int row = f >> 6;
        int col = (f & 63) * 4;
        int kg  = k0 + col;
        const float* src;
        if (mode == 0) {
            src = (kg < 512) ? g_emb + ((size_t)t*B + row)*DW + kg
                             : g_ctx + row*DE + (kg - 512);
        } else if (mode == 1) {
            src = g_h + row*DM + kg;
        } else {
            if (kg < 512)       src = g_emb + ((size_t)(t-1)*B + row)*DW + kg;
            else if (kg < 1024) src = g_h   + row*DM + (kg - 512);
            else                src = g_ctx + row*DE + (kg - 1024);
        }
        *(float4*)&sAct[row][col] = *(const float4*)src;
    }
    __syncthreads();

    int n  = n0 + tx * 4;
    int b0 = ty * 2;
    const float* wp = W + (size_t)k0 * stride + n;
    float4 a0 = make_float4(0.f,0.f,0.f,0.f);
    float4 a1 = make_float4(0.f,0.f,0.f,0.f);

#pragma unroll 8
    for (int k = 0; k < 256; k++) {
        float4 wv = *(const float4*)(wp + (size_t)k * stride);
        float x0 = sAct[b0][k];
        float x1 = sAct[b0+1][k];
        a0.x = fmaf(x0,wv.x,a0.x); a0.y = fmaf(x0,wv.y,a0.y);
        a0.z = fmaf(x0,wv.z,a0.z); a0.w = fmaf(x0,wv.w,a0.w);
        a1.x = fmaf(x1,wv.x,a1.x); a1.y = fmaf(x1,wv.y,a1.y);
        a1.z = fmaf(x1,wv.z,a1.z); a1.w = fmaf(x1,wv.w,a1.w);
    }

    if (mode == 0) {
        *(float4*)(g_gxp[ks] + (size_t)b0*G3 + n)     = a0;
        *(float4*)(g_gxp[ks] + (size_t)(b0+1)*G3 + n) = a1;
    } else if (mode == 1) {
        *(float4*)(g_ghp[ks] + (size_t)b0*G3 + n)     = a0;
        *(float4*)(g_ghp[ks] + (size_t)(b0+1)*G3 + n) = a1;
    } else {
        *(float4*)(g_rop[ks] + (size_t)b0*DM + n)     = a0;
        *(float4*)(g_rop[ks] + (size_t)(b0+1)*DM + n) = a1;
    }
}

// ---------------- per-step attention megakernel (1024 thr / batch row) ---------
__global__ void k_attn(int t,
                       const int*   __restrict__ src_seq,
                       const float* __restrict__ enc,
                       const float* __restrict__ Wq,
                       const float* __restrict__ w_cov,
                       const float* __restrict__ v_att,
                       const float* __restrict__ W_copy,
                       const float* __restrict__ b_copy,
                       const float* __restrict__ bx,
                       const float* __restrict__ bh,
                       const float* __restrict__ b_read,
                       float* __restrict__ out)
{
    int b   = blockIdx.x;
    int tid = threadIdx.x;                 // 0..1023

    __shared__ float sh[DM];
    __shared__ float sq[DK];
    __shared__ float sqp[16][DK];
    __shared__ float swc[DK];
    __shared__ float sva[DK];
    __shared__ float ss[S];
    __shared__ float red[1024];
    __shared__ float sctx[DE];
    __shared__ float spart[7][DE];

    // ---- readout reduce + maxout for step t-1 (independent side phase) ----
    if (t > 0 && tid < 256) {
        float2 acc = *(const float2*)(b_read + tid*2);
#pragma unroll
        for (int p = 0; p < 6; p++) {
            float2 v = *(const float2*)(g_rop[p] + (size_t)b*DM + tid*2);
            acc.x += v.x; acc.y += v.y;
        }
        out[OFF_PRED + ((size_t)b*T + (t-1)) * (DM/2) + tid] = fmaxf(acc.x, acc.y);
    }

    // ---- GRU gates -> h_new ----
    if (tid < DM) {
        int j = tid;
        size_t base = (size_t)b*G3 + j;
        float gxr = bx[j],        ghr = bh[j];
        float gxz = bx[DM+j],     ghz = bh[DM+j];
        float gxn = bx[2*DM+j],   ghn = bh[2*DM+j];
#pragma unroll
        for (int p = 0; p < 4; p++) {
            gxr += g_gxp[p][base];
            gxz += g_gxp[p][base + DM];
            gxn += g_gxp[p][base + 2*DM];
        }
#pragma unroll
        for (int p = 0; p < 2; p++) {
            ghr += g_ghp[p][base];
            ghz += g_ghp[p][base + DM];
            ghn += g_ghp[p][base + 2*DM];
        }
        float r  = sigmoid_fast(gxr + ghr);
        float z  = sigmoid_fast(gxz + ghz);
        float nn = tanh_fast(gxn + r * ghn);
        float ho = g_h[b*DM + j];
        float hn = (1.f - z) * nn + z * ho;
        sh[j] = hn;
        g_h[b*DM + j] = hn;
    }
    __syncthreads();

    // ---- q = h_new @ Wq  (split-K over 16 parts) ----
    {
        int j = tid & 63, p = tid >> 6;     // p 0..15
        float acc = 0.f;
        for (int k = p*32; k < (p+1)*32; k++)
            acc = fmaf(sh[k], Wq[k*DK + j], acc);
        sqp[p][j] = acc;
        if (tid < DK)          swc[tid]      = w_cov[tid];
        else if (tid < 2*DK)   sva[tid - DK] = v_att[tid - DK];
    }
    __syncthreads();
    if (tid < DK) {
        float s = 0.f;
#pragma unroll
        for (int p = 0; p < 16; p++) s += sqp[p][tid];
        sq[tid] = s;
    }
    __syncthreads();

    // ---- attention scores with coverage + pad mask ----
    if (tid < S) {
        int s = tid;
        float cv = g_cov[b*S + s];
        const float* pr = g_pre + ((size_t)b*S + s) * DK;
        float acc = 0.f;
#pragma unroll 8
        for (int k = 0; k < DK; k++)
            acc = fmaf(tanh_fast(pr[k] + sq[k] + cv * swc[k]), sva[k], acc);
        if (src_seq[b*S + s] == PAD_ID) acc = -1e9f;
        ss[s] = acc;
    }
    __syncthreads();

    // ---- softmax over S ----
    float m = (tid < S) ? ss[tid] : -1e30f;
    red[tid] = m; __syncthreads();
    for (int w = 512; w > 0; w >>= 1) {
        if (tid < w) red[tid] = fmaxf(red[tid], red[tid+w]);
        __syncthreads();
    }
    m = red[0]; __syncthreads();

    float sum = 0.f;
    if (tid < S) { float e = __expf(ss[tid] - m); ss[tid] = e; sum = e; }
    red[tid] = sum; __syncthreads();
    for (int w = 512; w > 0; w >>= 1) {
        if (tid < w) red[tid] += red[tid+w];
        __syncthreads();
    }
    float inv = 1.f / red[0]; __syncthreads();

    // ---- attn, coverage update, outputs ----
    float cl = 0.f;
    float tden = fmaxf((float)t, 1.f);
    if (tid < S) {
        int s = tid;
        float a = ss[s] * inv; ss[s] = a;
        float cv = g_cov[b*S + s];
        cl = fminf(a, cv / tden);
        g_cov[b*S + s] = cv + a;
        out[OFF_COPY + (size_t)b*T*S + (size_t)t*S + s] = a;
        if (t == T-1) out[OFF_ATTNLAST + b*S + s] = a;
    }
    red[tid] = cl; __syncthreads();
    for (int w = 512; w > 0; w >>= 1) {
        if (tid < w) red[tid] += red[tid+w];
        __syncthreads();
    }
    if (tid == 0) out[OFF_COVP + b*T + t] = red[0];
    __syncthreads();

    // ---- new_ctx = attn @ enc  (128 float4 cols x 8 s-slices of 50) ----
    {
        int d4 = tid & 127;
        int q  = tid >> 7;                      // 0..7
        const float4* e4 = (const float4*)(enc + (size_t)b*S*DE);
        float4 acc = make_float4(0.f,0.f,0.f,0.f);
        int s0 = q * 50, s1 = s0 + 50;
#pragma unroll 5
        for (int s = s0; s < s1; s++) {
            float a = ss[s];
            float4 v = e4[(size_t)s*(DE/4) + d4];
            acc.x = fmaf(a,v.x,acc.x); acc.y = fmaf(a,v.y,acc.y);
            acc.z = fmaf(a,v.z,acc.z); acc.w = fmaf(a,v.w,acc.w);
        }
        if (q > 0) *(float4*)(&spart[q-1][d4*4]) = acc;
        __syncthreads();
        if (q == 0) {
#pragma unroll
            for (int p = 0; p < 7; p++) {
                float4 v = *(float4*)(&spart[p][d4*4]);
                acc.x += v.x; acc.y += v.y; acc.z += v.z; acc.w += v.w;
            }
            *(float4*)(&sctx[d4*4]) = acc;
            *(float4*)(g_ctx + b*DE + d4*4) = acc;
            if (t == T-1)
                *(float4*)(out + OFF_CTXF + b*DE + d4*4) = acc;
        }
        __syncthreads();
    }

    // ---- copy_gate = sigmoid([h_new, new_ctx] @ W_copy + b_copy) ----
    {
        float g = 0.f;
        if (tid < DM) g = fmaf(sh[tid], W_copy[tid], 0.f)
                        + sctx[tid] * W_copy[DM + tid];
        red[tid] = g; __syncthreads();
        for (int w = 512; w > 0; w >>= 1) {
            if (tid < w) red[tid] += red[tid+w];
            __syncthreads();
        }
        if (tid == 0) {
            float v = red[0] + b_copy[0];
            out[OFF_GATE + b*T + t] = sigmoid_fast(v);
        }
    }
}

// final readout reduce for t = T-1
__global__ void k_rofin(const float* __restrict__ b_read, float* __restrict__ out)
{
    int b = blockIdx.x, tid = threadIdx.x;   // 32 blocks x 256
    float2 acc = *(const float2*)(b_read + tid*2);
#pragma unroll
    for (int p = 0; p < 6; p++) {
        float2 v = *(const float2*)(g_rop[p] + (size_t)b*DM + tid*2);
        acc.x += v.x; acc.y += v.y;
    }
    out[OFF_PRED + ((size_t)b*T + (T-1)) * (DM/2) + tid] = fmaxf(acc.x, acc.y);
}

// ---------------- launch ------------------------------------------------------

extern "C" void kernel_launch(void* const* d_in, const int* in_sizes, int n_in,
                              void* d_out, int out_size)
{
    const int*   tgt      = (const int*)  d_in[0];
    const int*   src      = (const int*)  d_in[1];
    const float* enc      = (const float*)d_in[2];
    const float* hidden   = (const float*)d_in[3];
    const float* word_emb = (const float*)d_in[4];
    const float* W_init   = (const float*)d_in[5];
    const float* b_init   = (const float*)d_in[6];
    const float* Wx       = (const float*)d_in[7];
    const float* Wh       = (const float*)d_in[8];
    const float* bx       = (const float*)d_in[9];
    const float* bh       = (const float*)d_in[10];
    const float* Wc       = (const float*)d_in[11];
    const float* Wq       = (const float*)d_in[12];
    const float* w_cov    = (const float*)d_in[13];
    const float* v_att    = (const float*)d_in[14];
    const float* W_copy   = (const float*)d_in[15];
    const float* b_copy   = (const float*)d_in[16];
    const float* W_read   = (const float*)d_in[17];
    const float* b_read   = (const float*)d_in[18];
    float* out = (float*)d_out;

    k_embed<<<T*B, 128>>>(tgt, word_emb);
    k_pre<<<(B*S)/16, dim3(16,16)>>>(enc, Wc);
    k_init<<<(B*DM)/256, 256>>>(hidden, W_init, b_init);

    for (int t = 0; t < T; t++) {
        k_big<<<192, dim3(16,16)>>>(t, Wx, Wh, W_read);
        k_attn<<<B, 1024>>>(t, src, enc, Wq, w_cov, v_att, W_copy, b_copy,
                            bx, bh, b_read, out);
    }
    k_big<<<192, dim3(16,16)>>>(T, Wx, Wh, W_read);   // readout for t=T-1
    k_rofin<<<B, 256>>>(b_read, out);
}

// round 6
// speedup vs baseline: 7.4676x; 1.7233x over previous
#include <cuda_runtime.h>
#include <math.h>

#define B   32
#define T   64
#define S   400
#define DW  512
#define DM  512
#define DE  512
#define DK  64
#define G3  (3*DM)          // 1536
#define PAD_ID 50256

// ---------------- scratch (device globals) ------------------------------------
__device__ float g_emb[T*B*DW];       // [T,B,DW]
__device__ float g_pre[B*S*DK];       // enc @ Wc
__device__ float g_h  [B*DM];
__device__ float g_ctx[B*DE];
__device__ float g_cov[B*S];
__device__ float g_gxp[8][B*G3];      // gx split-K partials
__device__ float g_ghp[4][B*G3];      // gh split-K partials
__device__ float g_rop[12][B*DM];     // readout split-K partials

// out layout (float32):
#define OFF_PRED      0
#define OFF_ATTNLAST  524288
#define OFF_CTXF      537088
#define OFF_COPY      553472
#define OFF_GATE      1372672
#define OFF_COVP      1374720

__device__ __forceinline__ float tanh_fast(float x) {
    float y; asm("tanh.approx.f32 %0, %1;" : "=f"(y) : "f"(x)); return y;
}
__device__ __forceinline__ float sigmoid_fast(float x) {
    return 1.f / (1.f + __expf(-x));
}

// block reductions for 512 threads (16 warps), via shuffles. sred[16].
__device__ __forceinline__ float bsum(float v, float* sred, int tid) {
    __syncthreads();                       // protect sred reuse
#pragma unroll
    for (int o = 16; o > 0; o >>= 1) v += __shfl_xor_sync(~0u, v, o);
    if ((tid & 31) == 0) sred[tid >> 5] = v;
    __syncthreads();
    if (tid < 32) {
        float x = (tid < 16) ? sred[tid] : 0.f;
#pragma unroll
        for (int o = 8; o > 0; o >>= 1) x += __shfl_xor_sync(~0u, x, o);
        if (tid == 0) sred[0] = x;
    }
    __syncthreads();
    return sred[0];
}
__device__ __forceinline__ float bmax(float v, float* sred, int tid) {
    __syncthreads();
#pragma unroll
    for (int o = 16; o > 0; o >>= 1) v = fmaxf(v, __shfl_xor_sync(~0u, v, o));
    if ((tid & 31) == 0) sred[tid >> 5] = v;
    __syncthreads();
    if (tid < 32) {
        float x = (tid < 16) ? sred[tid] : -1e30f;
#pragma unroll
        for (int o = 8; o > 0; o >>= 1) x = fmaxf(x, __shfl_xor_sync(~0u, x, o));
        if (tid == 0) sred[0] = x;
    }
    __syncthreads();
    return sred[0];
}

// ---------------- one-time kernels -------------------------------------------

__global__ void k_embed(const int* __restrict__ tgt, const float* __restrict__ word_emb)
{
    int row = blockIdx.x;                 // row = t*B + b
    int t = row / B, b = row % B;
    int id = tgt[b*T + t];
    const float4* src = (const float4*)(word_emb + (long long)id * DW);
    float4* dst = (float4*)(g_emb + (long long)row * DW);
    dst[threadIdx.x] = src[threadIdx.x];  // 128 threads * float4
}

__global__ void k_pre(const float* __restrict__ enc, const float* __restrict__ Wc)
{
    int row = blockIdx.x * 16 + threadIdx.y;        // grid 800, block (16,16)
    int n   = threadIdx.x * 4;
    const float* a = enc + (long long)row * DE;
    float4 acc = make_float4(0.f,0.f,0.f,0.f);
#pragma unroll 8
    for (int k = 0; k < DE; k++) {
        float av = a[k];
        float4 wv = *(const float4*)(Wc + k*DK + n);
        acc.x = fmaf(av, wv.x, acc.x); acc.y = fmaf(av, wv.y, acc.y);
        acc.z = fmaf(av, wv.z, acc.z); acc.w = fmaf(av, wv.w, acc.w);
    }
    *(float4*)(g_pre + (long long)row*DK + n) = acc;
}

__global__ void k_init(const float* __restrict__ hidden,
                       const float* __restrict__ W_init,
                       const float* __restrict__ b_init)
{
    int idx = blockIdx.x * 256 + threadIdx.x;   // 0..16383
    int b = idx / DM, j = idx % DM;
    const float* a = hidden + b * DE;
    float acc = b_init[j];
#pragma unroll 8
    for (int k = 0; k < DE; k++)
        acc = fmaf(a[k], W_init[k*DM + j], acc);
    g_h[idx]   = tanhf(acc);
    g_ctx[idx] = 0.f;
    if (idx < B*S) g_cov[idx] = 0.f;
}

// ---------------- per-step GEMM kernel (768 blocks) ---------------------------
// block (8,16) = 128 thr: tx -> 4 n-cols, ty -> 2 batch rows. K-chunk 128.
// bid [0,384):   gx  48 n-tiles x 8 k-chunks  (Wx, K=1024)
// bid [384,576): gh  48 n-tiles x 4 k-chunks  (Wh, K=512)
// bid [576,768): ro  16 n-tiles x 12 k-chunks (W_read, K=1536) for step t-1
__global__ void k_big(int t,
                      const float* __restrict__ Wx, const float* __restrict__ Wh,
                      const float* __restrict__ W_read)
{
    __shared__ float sAct[32][132];

    int bid = blockIdx.x;
    int tx = threadIdx.x;      // 0..7
    int ty = threadIdx.y;      // 0..15
    int tid = ty*8 + tx;

    const float* W; int n0, k0, stride, ks, mode;
    if (bid < 384) {
        if (t >= T) return;
        mode = 0; ks = bid & 7; n0 = (bid >> 3) * 32; k0 = ks * 128;
        W = Wx; stride = G3;
    } else if (bid < 576) {
        if (t >= T) return;
        int r = bid - 384;
        mode = 1; ks = r & 3; n0 = (r >> 2) * 32; k0 = ks * 128;
        W = Wh; stride = G3;
    } else {
        if (t == 0) return;
        int r = bid - 576;
        mode = 2; ks = r % 12; n0 = (r / 12) * 32; k0 = ks * 128;
        W = W_read; stride = DM;
    }

    // cooperative load of act chunk [32][128] (1024 float4 / 128 thr = 8 each)
#pragma unroll
    for (int j = 0; j < 8; j++) {
        int f   = tid + j * 128;
        int row = f >> 5;
        int col = (f & 31) * 4;
        int kg  = k0 + col;
        const float* src;
        if (mode == 0) {
            src = (kg < 512) ? g_emb + ((size_t)t*B + row)*DW + kg
                             : g_ctx + row*DE + (kg - 512);
        } else if (mode == 1) {
            src = g_h + row*DM + kg;
        } else {
            if (kg < 512)       src = g_emb + ((size_t)(t-1)*B + row)*DW + kg;
            else if (kg < 1024) src = g_h   + row*DM + (kg - 512);
            else                src = g_ctx + row*DE + (kg - 1024);
        }
        *(float4*)&sAct[row][col] = *(const float4*)src;
    }
    __syncthreads();

    int n  = n0 + tx * 4;
    int b0 = ty * 2;
    const float* wp = W + (size_t)k0 * stride + n;
    float4 a0 = make_float4(0.f,0.f,0.f,0.f);
    float4 a1 = make_float4(0.f,0.f,0.f,0.f);

#pragma unroll 4
    for (int k = 0; k < 128; k += 4) {
        float4 x0 = *(const float4*)&sAct[b0][k];
        float4 x1 = *(const float4*)&sAct[b0+1][k];
        float4 w0 = *(const float4*)(wp + (size_t)(k  ) * stride);
        float4 w1 = *(const float4*)(wp + (size_t)(k+1) * stride);
        float4 w2 = *(const float4*)(wp + (size_t)(k+2) * stride);
        float4 w3 = *(const float4*)(wp + (size_t)(k+3) * stride);
        a0.x = fmaf(x0.x,w0.x,a0.x); a0.y = fmaf(x0.x,w0.y,a0.y);
        a0.z = fmaf(x0.x,w0.z,a0.z); a0.w = fmaf(x0.x,w0.w,a0.w);
        a1.x = fmaf(x1.x,w0.x,a1.x); a1.y = fmaf(x1.x,w0.y,a1.y);
        a1.z = fmaf(x1.x,w0.z,a1.z); a1.w = fmaf(x1.x,w0.w,a1.w);
        a0.x = fmaf(x0.y,w1.x,a0.x); a0.y = fmaf(x0.y,w1.y,a0.y);
        a0.z = fmaf(x0.y,w1.z,a0.z); a0.w = fmaf(x0.y,w1.w,a0.w);
        a1.x = fmaf(x1.y,w1.x,a1.x); a1.y = fmaf(x1.y,w1.y,a1.y);
        a1.z = fmaf(x1.y,w1.z,a1.z); a1.w = fmaf(x1.y,w1.w,a1.w);
        a0.x = fmaf(x0.z,w2.x,a0.x); a0.y = fmaf(x0.z,w2.y,a0.y);
        a0.z = fmaf(x0.z,w2.z,a0.z); a0.w = fmaf(x0.z,w2.w,a0.w);
        a1.x = fmaf(x1.z,w2.x,a1.x); a1.y = fmaf(x1.z,w2.y,a1.y);
        a1.z = fmaf(x1.z,w2.z,a1.z); a1.w = fmaf(x1.z,w2.w,a1.w);
        a0.x = fmaf(x0.w,w3.x,a0.x); a0.y = fmaf(x0.w,w3.y,a0.y);
        a0.z = fmaf(x0.w,w3.z,a0.z); a0.w = fmaf(x0.w,w3.w,a0.w);
        a1.x = fmaf(x1.w,w3.x,a1.x); a1.y = fmaf(x1.w,w3.y,a1.y);
        a1.z = fmaf(x1.w,w3.z,a1.z); a1.w = fmaf(x1.w,w3.w,a1.w);
    }

    if (mode == 0) {
        *(float4*)(g_gxp[ks] + (size_t)b0*G3 + n)     = a0;
        *(float4*)(g_gxp[ks] + (size_t)(b0+1)*G3 + n) = a1;
    } else if (mode == 1) {
        *(float4*)(g_ghp[ks] + (size_t)b0*G3 + n)     = a0;
        *(float4*)(g_ghp[ks] + (size_t)(b0+1)*G3 + n) = a1;
    } else {
        *(float4*)(g_rop[ks] + (size_t)b0*DM + n)     = a0;
        *(float4*)(g_rop[ks] + (size_t)(b0+1)*DM + n) = a1;
    }
}

// ---------------- per-step attention megakernel (512 thr / batch row) ---------
__global__ void k_attn(int t,
                       const int*   __restrict__ src_seq,
                       const float* __restrict__ enc,
                       const float* __restrict__ Wq,
                       const float* __restrict__ w_cov,
                       const float* __restrict__ v_att,
                       const float* __restrict__ W_copy,
                       const float* __restrict__ b_copy,
                       const float* __restrict__ bx,
                       const float* __restrict__ bh,
                       const float* __restrict__ b_read,
                       float* __restrict__ out)
{
    int b   = blockIdx.x;
    int tid = threadIdx.x;                 // 0..511

    __shared__ float sh[DM];
    __shared__ float sq[DK];
    __shared__ float sqp[8][DK];
    __shared__ float swc[DK];
    __shared__ float sva[DK];
    __shared__ float ss[S];
    __shared__ float sred[16];
    __shared__ float sctx[DE];
    __shared__ float spart[3][DE];

    // ---- readout reduce + maxout for step t-1 (independent side phase) ----
    if (t > 0 && tid < 256) {
        float2 acc = *(const float2*)(b_read + tid*2);
#pragma unroll
        for (int p = 0; p < 12; p++) {
            float2 v = *(const float2*)(g_rop[p] + (size_t)b*DM + tid*2);
            acc.x += v.x; acc.y += v.y;
        }
        out[OFF_PRED + ((size_t)b*T + (t-1)) * (DM/2) + tid] = fmaxf(acc.x, acc.y);
    }

    // ---- GRU gates -> h_new ----
    {
        int j = tid;
        size_t base = (size_t)b*G3 + j;
        float gxr = bx[j],        ghr = bh[j];
        float gxz = bx[DM+j],     ghz = bh[DM+j];
        float gxn = bx[2*DM+j],   ghn = bh[2*DM+j];
#pragma unroll
        for (int p = 0; p < 8; p++) {
            gxr += g_gxp[p][base];
            gxz += g_gxp[p][base + DM];
            gxn += g_gxp[p][base + 2*DM];
        }
#pragma unroll
        for (int p = 0; p < 4; p++) {
            ghr += g_ghp[p][base];
            ghz += g_ghp[p][base + DM];
            ghn += g_ghp[p][base + 2*DM];
        }
        float r  = sigmoid_fast(gxr + ghr);
        float z  = sigmoid_fast(gxz + ghz);
        float nn = tanh_fast(gxn + r * ghn);
        float ho = g_h[b*DM + j];
        float hn = (1.f - z) * nn + z * ho;
        sh[j] = hn;
        g_h[b*DM + j] = hn;
    }
    __syncthreads();

    // ---- q = h_new @ Wq  (split-K over 8 parts of 64) ----
    {
        int j = tid & 63, p = tid >> 6;     // p 0..7
        float acc = 0.f;
#pragma unroll 8
        for (int k = p*64; k < (p+1)*64; k++)
            acc = fmaf(sh[k], Wq[k*DK + j], acc);
        sqp[p][j] = acc;
        if (tid < DK)          swc[tid]      = w_cov[tid];
        else if (tid < 2*DK)   sva[tid - DK] = v_att[tid - DK];
    }
    __syncthreads();
    if (tid < DK) {
        float s = 0.f;
#pragma unroll
        for (int p = 0; p < 8; p++) s += sqp[p][tid];
        sq[tid] = s;
    }
    __syncthreads();

    // ---- attention scores with coverage + pad mask ----
    float cv = 0.f;
    if (tid < S) {
        cv = g_cov[b*S + tid];
        const float4* pr = (const float4*)(g_pre + ((size_t)b*S + tid) * DK);
        float acc = 0.f;
#pragma unroll
        for (int k4 = 0; k4 < 16; k4++) {
            float4 p = pr[k4];
            int k = k4*4;
            acc = fmaf(tanh_fast(p.x + sq[k  ] + cv*swc[k  ]), sva[k  ], acc);
            acc = fmaf(tanh_fast(p.y + sq[k+1] + cv*swc[k+1]), sva[k+1], acc);
            acc = fmaf(tanh_fast(p.z + sq[k+2] + cv*swc[k+2]), sva[k+2], acc);
            acc = fmaf(tanh_fast(p.w + sq[k+3] + cv*swc[k+3]), sva[k+3], acc);
        }
        if (src_seq[b*S + tid] == PAD_ID) acc = -1e9f;
        ss[tid] = acc;
    }

    // ---- softmax over S ----
    float m = bmax((tid < S) ? ss[tid] : -1e30f, sred, tid);
    float e = 0.f;
    if (tid < S) { e = __expf(ss[tid] - m); }
    float inv = 1.f / bsum(e, sred, tid);

    // ---- attn, coverage update, outputs ----
    float cl = 0.f;
    float tden = fmaxf((float)t, 1.f);
    if (tid < S) {
        float a = e * inv; ss[tid] = a;
        cl = fminf(a, cv / tden);
        g_cov[b*S + tid] = cv + a;
        out[OFF_COPY + (size_t)b*T*S + (size_t)t*S + tid] = a;
        if (t == T-1) out[OFF_ATTNLAST + b*S + tid] = a;
    }
    float clsum = bsum(cl, sred, tid);
    if (tid == 0) out[OFF_COVP + b*T + t] = clsum;
    __syncthreads();

    // ---- new_ctx = attn @ enc  (128 float4 cols x 4 s-slices of 100) ----
    {
        int d4 = tid & 127;
        int q  = tid >> 7;                      // 0..3
        const float4* e4 = (const float4*)(enc + (size_t)b*S*DE);
        float4 acc = make_float4(0.f,0.f,0.f,0.f);
        int s0 = q * 100, s1 = s0 + 100;
#pragma unroll 4
        for (int s = s0; s < s1; s++) {
            float a = ss[s];
            float4 v = e4[(size_t)s*(DE/4) + d4];
            acc.x = fmaf(a,v.x,acc.x); acc.y = fmaf(a,v.y,acc.y);
            acc.z = fmaf(a,v.z,acc.z); acc.w = fmaf(a,v.w,acc.w);
        }
        if (q > 0) *(float4*)(&spart[q-1][d4*4]) = acc;
        __syncthreads();
        if (q == 0) {
#pragma unroll
            for (int p = 0; p < 3; p++) {
                float4 v = *(float4*)(&spart[p][d4*4]);
                acc.x += v.x; acc.y += v.y; acc.z += v.z; acc.w += v.w;
            }
            *(float4*)(&sctx[d4*4]) = acc;
            *(float4*)(g_ctx + b*DE + d4*4) = acc;
            if (t == T-1)
                *(float4*)(out + OFF_CTXF + b*DE + d4*4) = acc;
        }
        __syncthreads();
    }

    // ---- copy_gate = sigmoid([h_new, new_ctx] @ W_copy + b_copy) ----
    {
        float g = sh[tid] * W_copy[tid] + sctx[tid] * W_copy[DM + tid];
        float gs = bsum(g, sred, tid);
        if (tid == 0)
            out[OFF_GATE + b*T + t] = sigmoid_fast(gs + b_copy[0]);
    }
}

// final readout reduce for t = T-1
__global__ void k_rofin(const float* __restrict__ b_read, float* __restrict__ out)
{
    int b = blockIdx.x, tid = threadIdx.x;   // 32 blocks x 256
    float2 acc = *(const float2*)(b_read + tid*2);
#pragma unroll
    for (int p = 0; p < 12; p++) {
        float2 v = *(const float2*)(g_rop[p] + (size_t)b*DM + tid*2);
        acc.x += v.x; acc.y += v.y;
    }
    out[OFF_PRED + ((size_t)b*T + (T-1)) * (DM/2) + tid] = fmaxf(acc.x, acc.y);
}

// ---------------- launch ------------------------------------------------------

extern "C" void kernel_launch(void* const* d_in, const int* in_sizes, int n_in,
                              void* d_out, int out_size)
{
    const int*   tgt      = (const int*)  d_in[0];
    const int*   src      = (const int*)  d_in[1];
    const float* enc      = (const float*)d_in[2];
    const float* hidden   = (const float*)d_in[3];
    const float* word_emb = (const float*)d_in[4];
    const float* W_init   = (const float*)d_in[5];
    const float* b_init   = (const float*)d_in[6];
    const float* Wx       = (const float*)d_in[7];
    const float* Wh       = (const float*)d_in[8];
    const float* bx       = (const float*)d_in[9];
    const float* bh       = (const float*)d_in[10];
    const float* Wc       = (const float*)d_in[11];
    const float* Wq       = (const float*)d_in[12];
    const float* w_cov    = (const float*)d_in[13];
    const float* v_att    = (const float*)d_in[14];
    const float* W_copy   = (const float*)d_in[15];
    const float* b_copy   = (const float*)d_in[16];
    const float* W_read   = (const float*)d_in[17];
    const float* b_read   = (const float*)d_in[18];
    float* out = (float*)d_out;

    k_embed<<<T*B, 128>>>(tgt, word_emb);
    k_pre<<<(B*S)/16, dim3(16,16)>>>(enc, Wc);
    k_init<<<(B*DM)/256, 256>>>(hidden, W_init, b_init);

    for (int t = 0; t < T; t++) {
        k_big<<<768, dim3(8,16)>>>(t, Wx, Wh, W_read);
        k_attn<<<B, 512>>>(t, src, enc, Wq, w_cov, v_att, W_copy, b_copy,
                           bx, bh, b_read, out);
    }
    k_big<<<768, dim3(8,16)>>>(T, Wx, Wh, W_read);   // readout for t=T-1
    k_rofin<<<B, 256>>>(b_read, out);
}